// round 5
// baseline (speedup 1.0000x reference)
#include <cuda_runtime.h>
#include <math_constants.h>

// ---------------- problem constants ----------------
#define BB 8
#define CC 256
#define HW 4096                    // 64*64
#define PIXTOT (BB*HW)             // 32768
#define NSPLIT 8
#define CPB (CC/NSPLIT)            // 32 channels per block
#define T1 128                     // threads in fused kernel
#define PIX 512                    // pixels per main block (4 per thread)
#define MAIN_BLOCKS 512            // 8 splits * 8 batches * 8 pixel-blocks
#define KL_BLOCKS 512
#define PIX_BLOCKS 128             // k_pix grid (must be <= 148 for grid barrier)

// ---------------- scratch (static device arrays; no dynamic alloc) ----------------
// per-pixel partials per split: q: 0 sq_opt 1 cos_opt 2 sq_het 3 cos_het 4 s_sum 5 t_sum 6 s_max 7 t_max
__device__ __align__(16) float g_P[NSPLIT][8][PIXTOT];         // 8 MB
__device__ __align__(16) float g_chanP_s[BB * 8 * CC];         // per (b,pb) per-channel partial
__device__ __align__(16) float g_chanP_t[BB * 8 * CC];
__device__ __align__(16) float g_glP[MAIN_BLOCKS];
__device__ __align__(16) float g_locP[MAIN_BLOCKS];
__device__ __align__(16) float g_klP[KL_BLOCKS];
__device__ __align__(16) float g_c1P[KL_BLOCKS];
__device__ __align__(16) float g_odA[PIX_BLOCKS];
__device__ __align__(16) float g_dP[PIX_BLOCKS];
__device__ __align__(16) float g_spP[PIX_BLOCKS];
__device__ __align__(16) float g_chfP[8];
__device__ __align__(16) float g_chlP[8];
__device__ __align__(16) float g_sc[4];                        // 0 gl 1 loc 2 kl 3 c1
__device__ unsigned g_cnt  = 0;                                // self-resetting
__device__ unsigned g_cnt2 = 0;

// ---------------- helpers ----------------
__device__ __forceinline__ float warp_sum(float v) {
#pragma unroll
    for (int o = 16; o; o >>= 1) v += __shfl_xor_sync(0xffffffffu, v, o);
    return v;
}

__device__ __forceinline__ float sigm(float x) {
    return __fdividef(1.f, 1.f + __expf(-x));
}

// cos term: x / max(|x|, 1e-8) == sign(x) when |x|>=1e-8, else x*1e8 (no MUFU)
__device__ __forceinline__ float cos_term(float a, float b) {
    const float x = a * b;
    const float s = __uint_as_float((__float_as_uint(x) & 0x80000000u) | 0x3f800000u);
    return (fabsf(x) >= 1e-8f) ? s : x * 1e8f;
}

// block reduce (<=256 threads, 8 warps) -> value valid on thread 0
__device__ __forceinline__ float block_sum(float v, float* smem8) {
    v = warp_sum(v);
    const int lane = threadIdx.x & 31;
    const int wid  = threadIdx.x >> 5;
    if (lane == 0) smem8[wid] = v;
    __syncthreads();
    float r = 0.f;
    if (threadIdx.x == 0) {
        const int nw = (blockDim.x + 31) >> 5;
        for (int i = 0; i < nw; i++) r += smem8[i];
    }
    __syncthreads();
    return r;
}

// ---------------- K1: fused big streamer (features/diff) + KL ----------------
__global__ __launch_bounds__(T1) void k_fused(
    const float* __restrict__ S, const float* __restrict__ Tt,
    const float* __restrict__ O1, const float* __restrict__ O2,
    const float* __restrict__ SA, const float* __restrict__ M,
    const float* __restrict__ SO, const float* __restrict__ TO)
{
    __shared__ float smem8[8];

    if (blockIdx.x < MAIN_BLOCKS) {
        // ---- main streamer role ----
        const int blk   = blockIdx.x;
        const int split = blk >> 6;           // 0..7
        const int rem   = blk & 63;
        const int b     = rem >> 3;           // 0..7
        const int pb    = rem & 7;            // 0..7
        const int c0    = split * CPB;
        const int px    = pb * PIX + threadIdx.x * 4;
        const size_t base = (size_t)b * CC * HW + (size_t)c0 * HW + px;

        const float4* sp  = (const float4*)(S  + base);
        const float4* tp  = (const float4*)(Tt + base);
        const float4* o1p = (const float4*)(O1 + base);
        const float4* o2p = (const float4*)(O2 + base);
        const float4* sap = (const float4*)(SA + base);

        float sqo[4] = {0,0,0,0}, cso[4] = {0,0,0,0};
        float sqh[4] = {0,0,0,0}, csh[4] = {0,0,0,0};
        float ssm[4] = {0,0,0,0}, tsm[4] = {0,0,0,0};
        float gl[4]  = {0,0,0,0};
        float smx[4] = {-CUDART_INF_F,-CUDART_INF_F,-CUDART_INF_F,-CUDART_INF_F};
        float tmx[4] = {-CUDART_INF_F,-CUDART_INF_F,-CUDART_INF_F,-CUDART_INF_F};

        const int lane = threadIdx.x & 31;
        const int wid  = threadIdx.x >> 5;            // 0..3
        __shared__ float sch[2][4][CPB];              // [s/t][warp][channel] partials

#pragma unroll 8
        for (int ci = 0; ci < CPB; ci++) {
            const int off = ci * (HW / 4);
            const float4 s  = sp[off];
            const float4 t  = tp[off];
            const float4 a  = o1p[off];
            const float4 b2 = o2p[off];
            const float4 c2 = sap[off];
            const float sv[4] = {s.x, s.y, s.z, s.w};
            const float tv[4] = {t.x, t.y, t.z, t.w};
            const float av[4] = {a.x, a.y, a.z, a.w};
            const float bv[4] = {b2.x, b2.y, b2.z, b2.w};
            const float cv[4] = {c2.x, c2.y, c2.z, c2.w};
#pragma unroll
            for (int k = 0; k < 4; k++) {
                const float d = sv[k] - tv[k];
                gl[k]  += d * d;
                ssm[k] += sv[k];
                tsm[k] += tv[k];
                smx[k] = fmaxf(smx[k], sv[k]);
                tmx[k] = fmaxf(tmx[k], tv[k]);
                const float d1 = av[k] - bv[k];
                sqo[k] += d1 * d1;
                cso[k] += cos_term(av[k], bv[k]);
                const float d2 = av[k] - cv[k];
                sqh[k] += d2 * d2;
                csh[k] += cos_term(av[k], cv[k]);
            }
            // per-channel warp partials over this warp's 128 pixels
            const float sred = warp_sum(sv[0] + sv[1] + sv[2] + sv[3]);
            const float tred = warp_sum(tv[0] + tv[1] + tv[2] + tv[3]);
            if (lane == 0) { sch[0][wid][ci] = sred; sch[1][wid][ci] = tred; }
        }

        const int g4 = (b * HW + px) >> 2;
        ((float4*)g_P[split][0])[g4] = make_float4(sqo[0], sqo[1], sqo[2], sqo[3]);
        ((float4*)g_P[split][1])[g4] = make_float4(cso[0], cso[1], cso[2], cso[3]);
        ((float4*)g_P[split][2])[g4] = make_float4(sqh[0], sqh[1], sqh[2], sqh[3]);
        ((float4*)g_P[split][3])[g4] = make_float4(csh[0], csh[1], csh[2], csh[3]);
        ((float4*)g_P[split][4])[g4] = make_float4(ssm[0], ssm[1], ssm[2], ssm[3]);
        ((float4*)g_P[split][5])[g4] = make_float4(tsm[0], tsm[1], tsm[2], tsm[3]);
        ((float4*)g_P[split][6])[g4] = make_float4(smx[0], smx[1], smx[2], smx[3]);
        ((float4*)g_P[split][7])[g4] = make_float4(tmx[0], tmx[1], tmx[2], tmx[3]);

        __syncthreads();
        if (threadIdx.x < CPB) {
            const int ci = threadIdx.x;
            g_chanP_s[((b << 3) + pb) * CC + c0 + ci] =
                sch[0][0][ci] + sch[0][1][ci] + sch[0][2][ci] + sch[0][3][ci];
        } else if (threadIdx.x < 2 * CPB) {
            const int ci = threadIdx.x - CPB;
            g_chanP_t[((b << 3) + pb) * CC + c0 + ci] =
                sch[1][0][ci] + sch[1][1][ci] + sch[1][2][ci] + sch[1][3][ci];
        }

        const float4 m4 = *(const float4*)(M + b * HW + px);
        const float mv[4] = {m4.x, m4.y, m4.z, m4.w};
        float glt = 0.f, loct = 0.f;
#pragma unroll
        for (int k = 0; k < 4; k++) { glt += gl[k]; loct += mv[k] * mv[k] * gl[k]; }

        glt = block_sum(glt, smem8);
        const float loct_b = block_sum(loct, smem8);
        if (threadIdx.x == 0) { g_glP[blk] = glt; g_locP[blk] = loct_b; }
    } else {
        // ---- KL role ----
        const int kid = blockIdx.x - MAIN_BLOCKS;   // 0..511
        float kls = 0.f, c1s = 0.f;
#pragma unroll
        for (int it = 0; it < 2; it++) {
            const int idx = kid * 256 + it * 128 + threadIdx.x;   // 0..131071
            const int b  = idx >> 14;
            const int i4 = idx & 16383;
            const size_t base = (size_t)b * 32768 + i4;

            const float4 s0 = ((const float4*)SO)[base];
            const float4 s1 = ((const float4*)SO)[base + 16384];
            const float4 t0 = ((const float4*)TO)[base];
            const float4 t1 = ((const float4*)TO)[base + 16384];
            const float s0v[4] = {s0.x, s0.y, s0.z, s0.w};
            const float s1v[4] = {s1.x, s1.y, s1.z, s1.w};
            const float t0v[4] = {t0.x, t0.y, t0.z, t0.w};
            const float t1v[4] = {t1.x, t1.y, t1.z, t1.w};
#pragma unroll
            for (int k = 0; k < 4; k++) {
                const float a0 = s0v[k] * 0.25f, a1 = s1v[k] * 0.25f;
                const float mx = fmaxf(a0, a1);
                const float lse = mx + __logf(__expf(a0 - mx) + __expf(a1 - mx));
                const float ls0 = a0 - lse, ls1 = a1 - lse;
                const float b0 = t0v[k] * 0.25f, b1 = t1v[k] * 0.25f;
                const float mt = fmaxf(b0, b1);
                const float e0 = __expf(b0 - mt), e1 = __expf(b1 - mt);
                const float Z = e0 + e1;
                const float lZ = __logf(Z);
                const float rz = __fdividef(1.f, Z);
                const float p0 = e0 * rz, p1 = e1 * rz;
                kls += p0 * ((b0 - mt - lZ) - ls0) + p1 * ((b1 - mt - lZ) - ls1);
                const float dd = __expf(ls1) - p1;
                c1s += dd * dd;
            }
        }
        const float r0 = block_sum(kls, smem8);
        const float r1 = block_sum(c1s, smem8);
        if (threadIdx.x == 0) { g_klP[kid] = r0; g_c1P[kid] = r1; }
    }
}

// ---------------- K2: split-combine + grid barrier + masked losses + final ----------------
__global__ __launch_bounds__(256) void k_pix(float* out, int out_size) {
    const int tid = threadIdx.x;
    const int bid = blockIdx.x;
    const int pix = bid * 256 + tid;            // 0..32767
    __shared__ float smem8[8];
    __shared__ float sbr;

    // ---- phase A: combine splits, compute per-pixel maps in registers ----
    float sqo = 0.f, cso = 0.f, sqh = 0.f, csh = 0.f, ssm = 0.f, tsm = 0.f;
    float smx = -CUDART_INF_F, tmx = -CUDART_INF_F;
#pragma unroll
    for (int sp = 0; sp < NSPLIT; sp++) {
        sqo += g_P[sp][0][pix];
        cso += g_P[sp][1][pix];
        sqh += g_P[sp][2][pix];
        csh += g_P[sp][3][pix];
        ssm += g_P[sp][4][pix];
        tsm += g_P[sp][5][pix];
        smx = fmaxf(smx, g_P[sp][6][pix]);
        tmx = fmaxf(tmx, g_P[sp][7][pix]);
    }
    const float l2o = sqrtf(sqo + 1e-6f);
    const float od  = (l2o + 1.f - cso * (1.f / 256.f)) * sigm(l2o * 5.f);
    const float l2h = sqrtf(sqh + 1e-6f);
    const float hd  = (l2h + 1.f - csh * (1.f / 256.f)) * sigm(l2h * 5.f);
    const float ssp = sigm(ssm * (1.f / 256.f) + smx);
    const float tsp = sigm(tsm * (1.f / 256.f) + tmx);

    const float odb = block_sum(od, smem8);
    if (tid == 0) g_odA[bid] = odb;

    // role extras (all-thread-uniform branches per block)
    if (bid < 8) {
        // channel losses: thread per (b,c)
        const int cc = bid * 256 + tid;          // 0..2047
        const int b = cc >> 8, c = cc & 255;
        float ss = 0.f, tt = 0.f;
#pragma unroll
        for (int pb = 0; pb < 8; pb++) {
            ss += g_chanP_s[((b << 3) + pb) * CC + c];
            tt += g_chanP_t[((b << 3) + pb) * CC + c];
        }
        const float ms = ss * (1.f / (float)HW);
        const float mt = tt * (1.f / (float)HW);
        const float d  = ms - mt;
        const float e  = sigm(ms) - sigm(mt);
        const float r0 = block_sum(d * d, smem8);
        const float r1 = block_sum(e * e, smem8);
        if (tid == 0) { g_chfP[bid] = r0; g_chlP[bid] = r1; }
    } else if (bid == 8) {
        // reduce per-block partials from k_fused
        const float a = g_glP[tid]  + g_glP[tid + 256];
        const float l = g_locP[tid] + g_locP[tid + 256];
        const float k = g_klP[tid]  + g_klP[tid + 256];
        const float c = g_c1P[tid]  + g_c1P[tid + 256];
        const float r0 = block_sum(a, smem8);
        const float r1 = block_sum(l, smem8);
        const float r2 = block_sum(k, smem8);
        const float r3 = block_sum(c, smem8);
        if (tid == 0) { g_sc[0] = r0; g_sc[1] = r1; g_sc[2] = r2; g_sc[3] = r3; }
    }

    // ---- grid barrier (all PIX_BLOCKS co-resident: 128 <= 148 SMs) ----
    __threadfence();
    if (tid == 0) {
        atomicAdd(&g_cnt, 1u);
        volatile unsigned* c = &g_cnt;
        while (*c < (unsigned)PIX_BLOCKS) { __nanosleep(64); }
    }
    __syncthreads();

    // ---- phase B: masked losses using global mean(opt_diff) ----
    float odp = (tid < PIX_BLOCKS) ? __ldcg(&g_odA[tid]) : 0.f;
    const float odsum = block_sum(odp, smem8);
    if (tid == 0) sbr = odsum;
    __syncthreads();
    const float mean_od = sbr * (1.f / 32768.f);
    const float thr = mean_od * 1.5f;
    const float aw  = sigm(mean_od * 10.f);

    const float mask = (od > thr) ? 1.f : 0.f;
    const float w = mask * 2.f + (1.f - mask) * 0.5f;
    const float dd = (hd - od) * w;
    const float amp = 1.f + aw * mask;
    const float sd = (ssp - tsp) * amp;

    const float rD = block_sum(dd * dd, smem8);
    const float rS = block_sum(sd * sd, smem8);
    if (tid == 0) { g_dP[bid] = rD; g_spP[bid] = rS; }

    // ---- final combine in last-finishing block ----
    __shared__ bool isLast;
    __threadfence();
    if (tid == 0) isLast = (atomicAdd(&g_cnt2, 1u) == (unsigned)(PIX_BLOCKS - 1));
    __syncthreads();
    if (isLast) {
        float dv = (tid < PIX_BLOCKS) ? __ldcg(&g_dP[tid])  : 0.f;
        float sv = (tid < PIX_BLOCKS) ? __ldcg(&g_spP[tid]) : 0.f;
        float cf = (tid < 8) ? __ldcg(&g_chfP[tid]) : 0.f;
        float cl = (tid < 8) ? __ldcg(&g_chlP[tid]) : 0.f;
        const float dif_t = block_sum(dv, smem8);
        const float sp_t  = block_sum(sv, smem8);
        const float chf_t = block_sum(cf, smem8);
        const float chl_t = block_sum(cl, smem8);
        if (tid == 0) {
            const float gl  = __ldcg(&g_sc[0]) * (1.f / 8388608.f);
            const float loc = __ldcg(&g_sc[1]) * (1.f / 8388608.f);
            const float chf = chf_t * (1.f / 2048.f);
            const float feat = 0.3f * gl + 0.5f * loc + 0.2f * chf;

            const float kl  = __ldcg(&g_sc[2]) * 2.f;             // (/B=8) * T^2=16
            const float c1  = __ldcg(&g_sc[3]) * (2.f / 524288.f);
            const float outl = kl + c1;

            const float dif = dif_t * (1.f / 32768.f);
            const float sp  = sp_t  * (1.f / 32768.f);
            const float chl = chl_t * (1.f / 2048.f);
            const float alpha = 0.5f * (1.f + 0.5f * aw);
            const float beta  = 0.3f * (1.f - 0.3f * aw);
            const float gamma = 0.2f * (1.f + 0.5f * aw);
            const float datt = alpha * dif + beta * chl + gamma * sp;

            const float total = 0.3f * feat + 0.4f * outl + 0.3f * datt;
            if (out_size > 0) out[0] = total;
            if (out_size > 1) out[1] = feat;
            if (out_size > 2) out[2] = outl;
            if (out_size > 3) out[3] = datt;

            // reset counters for next graph replay (deterministic)
            g_cnt = 0u;
            g_cnt2 = 0u;
        }
    }
}

// ---------------- launch ----------------
extern "C" void kernel_launch(void* const* d_in, const int* in_sizes, int n_in,
                              void* d_out, int out_size) {
    const float* S  = (const float*)d_in[0];   // student_features
    const float* Tt = (const float*)d_in[1];   // teacher_features
    const float* SO = (const float*)d_in[2];   // student_outputs
    const float* TO = (const float*)d_in[3];   // teacher_outputs
    const float* O1 = (const float*)d_in[4];   // opt_t1
    const float* O2 = (const float*)d_in[5];   // opt_t2
    const float* SA = (const float*)d_in[6];   // sar_t2
    const float* M  = (const float*)d_in[7];   // feature_mask
    (void)in_sizes; (void)n_in;

    k_fused<<<MAIN_BLOCKS + KL_BLOCKS, T1>>>(S, Tt, O1, O2, SA, M, SO, TO);
    k_pix<<<PIX_BLOCKS, 256>>>((float*)d_out, out_size);
}

// round 6
// speedup vs baseline: 1.1838x; 1.1838x over previous
#include <cuda_runtime.h>
#include <math_constants.h>

// ---------------- problem constants ----------------
#define BB 8
#define CC 256
#define HW 4096                    // 64*64
#define PIXTOT (BB*HW)             // 32768
#define TPB 256
#define MAINB 256                  // 8 batches * 32 pixel-blocks (128 px each)
#define KLB 256                    // KL blocks
#define EPIB 128                   // epilogue blocks (256 px each)

// ---------------- scratch (static; no dynamic alloc) ----------------
__device__ __align__(16) float g_chanP_s[MAINB * CC];   // [blk][c] 256KB
__device__ __align__(16) float g_chanP_t[MAINB * CC];
__device__ __align__(16) float g_od[PIXTOT];
__device__ __align__(16) float g_hd[PIXTOT];
__device__ __align__(16) float g_ssp[PIXTOT];
__device__ __align__(16) float g_tsp[PIXTOT];
__device__ __align__(16) float g_odP[MAINB];
__device__ __align__(16) float g_glP[MAINB];
__device__ __align__(16) float g_locP[MAINB];
__device__ __align__(16) float g_klP[KLB];
__device__ __align__(16) float g_c1P[KLB];
__device__ __align__(16) float g_dP[EPIB];
__device__ __align__(16) float g_spP[EPIB];
__device__ __align__(16) float g_chfP[8];
__device__ __align__(16) float g_chlP[8];
__device__ __align__(16) float g_sc[4];                 // 0 gl 1 loc 2 kl 3 c1
__device__ unsigned g_cnt2 = 0;                         // self-resetting

// ---------------- helpers ----------------
__device__ __forceinline__ float warp_sum(float v) {
#pragma unroll
    for (int o = 16; o; o >>= 1) v += __shfl_xor_sync(0xffffffffu, v, o);
    return v;
}

__device__ __forceinline__ float sigm(float x) {
    return __fdividef(1.f, 1.f + __expf(-x));
}

// cos term: x / max(|x|, 1e-8) == sign(x) when |x|>=1e-8, else x*1e8 (no MUFU)
__device__ __forceinline__ float cos_term(float a, float b) {
    const float x = a * b;
    const float s = __uint_as_float((__float_as_uint(x) & 0x80000000u) | 0x3f800000u);
    return (fabsf(x) >= 1e-8f) ? s : x * 1e8f;
}

// block reduce (256 threads, 8 warps) -> value valid on thread 0; all threads must call
__device__ __forceinline__ float block_sum(float v, float* smem8) {
    v = warp_sum(v);
    const int lane = threadIdx.x & 31;
    const int wid  = threadIdx.x >> 5;
    if (lane == 0) smem8[wid] = v;
    __syncthreads();
    float r = 0.f;
    if (threadIdx.x == 0) {
#pragma unroll
        for (int i = 0; i < 8; i++) r += smem8[i];
    }
    __syncthreads();
    return r;
}

// ---------------- K1: fused streamer (all channels in-block) + KL ----------------
__global__ __launch_bounds__(TPB) void k_fused(
    const float* __restrict__ S, const float* __restrict__ Tt,
    const float* __restrict__ O1, const float* __restrict__ O2,
    const float* __restrict__ SA, const float* __restrict__ M,
    const float* __restrict__ SO, const float* __restrict__ TO)
{
    __shared__ float smem8[8];

    if (blockIdx.x < MAINB) {
        // ---- main role: 128 contiguous pixels, all 256 channels ----
        __shared__ float sAcc[8][9][128];     // [warp][quant][pixel] 36 KB
        const int blk = blockIdx.x;
        const int b   = blk >> 5;             // 0..7
        const int pb  = blk & 31;             // 0..31
        const int px0 = pb * 128;
        const int w    = threadIdx.x >> 5;    // 0..7
        const int lane = threadIdx.x & 31;
        const size_t pbase = (size_t)b * CC * HW + px0 + lane * 4;

        float sqo[4]={0,0,0,0}, cso[4]={0,0,0,0}, sqh[4]={0,0,0,0}, csh[4]={0,0,0,0};
        float ssm[4]={0,0,0,0}, tsm[4]={0,0,0,0}, gl[4]={0,0,0,0};
        float smx[4]={-CUDART_INF_F,-CUDART_INF_F,-CUDART_INF_F,-CUDART_INF_F};
        float tmx[4]={-CUDART_INF_F,-CUDART_INF_F,-CUDART_INF_F,-CUDART_INF_F};

#pragma unroll 4
        for (int j = 0; j < CC / 8; j++) {    // warp w handles channel c = w + 8j
            const int c = w + (j << 3);
            const size_t base = pbase + (size_t)c * HW;
            const float4 s  = *(const float4*)(S  + base);
            const float4 t  = *(const float4*)(Tt + base);
            const float4 a  = *(const float4*)(O1 + base);
            const float4 b2 = *(const float4*)(O2 + base);
            const float4 c2 = *(const float4*)(SA + base);
            const float sv[4] = {s.x, s.y, s.z, s.w};
            const float tv[4] = {t.x, t.y, t.z, t.w};
            const float av[4] = {a.x, a.y, a.z, a.w};
            const float bv[4] = {b2.x, b2.y, b2.z, b2.w};
            const float cv[4] = {c2.x, c2.y, c2.z, c2.w};
#pragma unroll
            for (int k = 0; k < 4; k++) {
                const float d = sv[k] - tv[k];
                gl[k]  += d * d;
                ssm[k] += sv[k];
                tsm[k] += tv[k];
                smx[k] = fmaxf(smx[k], sv[k]);
                tmx[k] = fmaxf(tmx[k], tv[k]);
                const float d1 = av[k] - bv[k];
                sqo[k] += d1 * d1;
                cso[k] += cos_term(av[k], bv[k]);
                const float d2 = av[k] - cv[k];
                sqh[k] += d2 * d2;
                csh[k] += cos_term(av[k], cv[k]);
            }
            // channel sum over this block's 128 pixels (complete for channel c)
            const float sred = warp_sum(sv[0] + sv[1] + sv[2] + sv[3]);
            const float tred = warp_sum(tv[0] + tv[1] + tv[2] + tv[3]);
            if (lane == 0) {
                g_chanP_s[blk * CC + c] = sred;
                g_chanP_t[blk * CC + c] = tred;
            }
        }

        // in-block cross-warp combine via smem transpose
        ((float4*)sAcc[w][0])[lane] = make_float4(sqo[0], sqo[1], sqo[2], sqo[3]);
        ((float4*)sAcc[w][1])[lane] = make_float4(cso[0], cso[1], cso[2], cso[3]);
        ((float4*)sAcc[w][2])[lane] = make_float4(sqh[0], sqh[1], sqh[2], sqh[3]);
        ((float4*)sAcc[w][3])[lane] = make_float4(csh[0], csh[1], csh[2], csh[3]);
        ((float4*)sAcc[w][4])[lane] = make_float4(ssm[0], ssm[1], ssm[2], ssm[3]);
        ((float4*)sAcc[w][5])[lane] = make_float4(tsm[0], tsm[1], tsm[2], tsm[3]);
        ((float4*)sAcc[w][6])[lane] = make_float4(gl[0],  gl[1],  gl[2],  gl[3]);
        ((float4*)sAcc[w][7])[lane] = make_float4(smx[0], smx[1], smx[2], smx[3]);
        ((float4*)sAcc[w][8])[lane] = make_float4(tmx[0], tmx[1], tmx[2], tmx[3]);
        __syncthreads();

        float odv = 0.f, glp = 0.f, locp = 0.f;
        if (threadIdx.x < 128) {
            const int p = threadIdx.x;
            float aSqo=0.f, aCso=0.f, aSqh=0.f, aCsh=0.f, aSsm=0.f, aTsm=0.f, aGl=0.f;
            float aSmx=-CUDART_INF_F, aTmx=-CUDART_INF_F;
#pragma unroll
            for (int w2 = 0; w2 < 8; w2++) {
                aSqo += sAcc[w2][0][p];
                aCso += sAcc[w2][1][p];
                aSqh += sAcc[w2][2][p];
                aCsh += sAcc[w2][3][p];
                aSsm += sAcc[w2][4][p];
                aTsm += sAcc[w2][5][p];
                aGl  += sAcc[w2][6][p];
                aSmx = fmaxf(aSmx, sAcc[w2][7][p]);
                aTmx = fmaxf(aTmx, sAcc[w2][8][p]);
            }
            const float l2o = sqrtf(aSqo + 1e-6f);
            const float od  = (l2o + 1.f - aCso * (1.f / 256.f)) * sigm(l2o * 5.f);
            const float l2h = sqrtf(aSqh + 1e-6f);
            const float hd  = (l2h + 1.f - aCsh * (1.f / 256.f)) * sigm(l2h * 5.f);
            const int gpix = b * HW + px0 + p;
            g_od[gpix]  = od;
            g_hd[gpix]  = hd;
            g_ssp[gpix] = sigm(aSsm * (1.f / 256.f) + aSmx);
            g_tsp[gpix] = sigm(aTsm * (1.f / 256.f) + aTmx);
            const float m = M[gpix];
            odv  = od;
            glp  = aGl;
            locp = m * m * aGl;
        }
        float r;
        r = block_sum(odv,  smem8); if (threadIdx.x == 0) g_odP[blk]  = r;
        r = block_sum(glp,  smem8); if (threadIdx.x == 0) g_glP[blk]  = r;
        r = block_sum(locp, smem8); if (threadIdx.x == 0) g_locP[blk] = r;
    } else {
        // ---- KL role ----
        const int kid = blockIdx.x - MAINB;   // 0..255
        float kls = 0.f, c1s = 0.f;
#pragma unroll
        for (int it = 0; it < 2; it++) {
            const int idx = kid * 512 + it * 256 + threadIdx.x;   // 0..131071
            const int b  = idx >> 14;
            const int i4 = idx & 16383;
            const size_t base = (size_t)b * 32768 + i4;

            const float4 s0 = ((const float4*)SO)[base];
            const float4 s1 = ((const float4*)SO)[base + 16384];
            const float4 t0 = ((const float4*)TO)[base];
            const float4 t1 = ((const float4*)TO)[base + 16384];
            const float s0v[4] = {s0.x, s0.y, s0.z, s0.w};
            const float s1v[4] = {s1.x, s1.y, s1.z, s1.w};
            const float t0v[4] = {t0.x, t0.y, t0.z, t0.w};
            const float t1v[4] = {t1.x, t1.y, t1.z, t1.w};
#pragma unroll
            for (int k = 0; k < 4; k++) {
                const float a0 = s0v[k] * 0.25f, a1 = s1v[k] * 0.25f;
                const float mx = fmaxf(a0, a1);
                const float lse = mx + __logf(__expf(a0 - mx) + __expf(a1 - mx));
                const float ls0 = a0 - lse, ls1 = a1 - lse;
                const float b0 = t0v[k] * 0.25f, b1 = t1v[k] * 0.25f;
                const float mt = fmaxf(b0, b1);
                const float e0 = __expf(b0 - mt), e1 = __expf(b1 - mt);
                const float Z = e0 + e1;
                const float lZ = __logf(Z);
                const float rz = __fdividef(1.f, Z);
                const float p0 = e0 * rz, p1 = e1 * rz;
                kls += p0 * ((b0 - mt - lZ) - ls0) + p1 * ((b1 - mt - lZ) - ls1);
                const float dd = __expf(ls1) - p1;
                c1s += dd * dd;
            }
        }
        const float r0 = block_sum(kls, smem8);
        const float r1 = block_sum(c1s, smem8);
        if (threadIdx.x == 0) { g_klP[kid] = r0; g_c1P[kid] = r1; }
    }
}

// ---------------- K2: epilogue (no grid barrier) ----------------
__global__ __launch_bounds__(256) void k_epi(float* out, int out_size) {
    __shared__ float smem8[8];
    __shared__ float sbr;
    const int tid = threadIdx.x;
    const int bid = blockIdx.x;

    // each block independently computes mean(opt_diff) from the 256 partials
    const float odsum = block_sum(g_odP[tid], smem8);
    if (tid == 0) sbr = odsum;
    __syncthreads();
    const float mean_od = sbr * (1.f / 32768.f);
    const float thr = mean_od * 1.5f;
    const float aw  = sigm(mean_od * 10.f);

    // masked diff + spatial losses (2 pixels worth per thread? no: 1 pixel, 128 blocks x 256)
    const int pix = bid * 256 + tid;            // 0..32767
    const float od  = g_od[pix];
    const float hd  = g_hd[pix];
    const float ssp = g_ssp[pix];
    const float tsp = g_tsp[pix];
    const float mask = (od > thr) ? 1.f : 0.f;
    const float w = mask * 2.f + (1.f - mask) * 0.5f;
    const float dd = (hd - od) * w;
    const float amp = 1.f + aw * mask;
    const float sd = (ssp - tsp) * amp;

    float r;
    r = block_sum(dd * dd, smem8); if (tid == 0) g_dP[bid]  = r;
    r = block_sum(sd * sd, smem8); if (tid == 0) g_spP[bid] = r;

    if (bid < 8) {
        // channel losses: b = bid, c = tid
        float ss = 0.f, tt = 0.f;
#pragma unroll
        for (int pb = 0; pb < 32; pb++) {
            ss += g_chanP_s[((bid << 5) + pb) * CC + tid];
            tt += g_chanP_t[((bid << 5) + pb) * CC + tid];
        }
        const float ms = ss * (1.f / (float)HW);
        const float mt = tt * (1.f / (float)HW);
        const float d  = ms - mt;
        const float e  = sigm(ms) - sigm(mt);
        const float r0 = block_sum(d * d, smem8);
        const float r1 = block_sum(e * e, smem8);
        if (tid == 0) { g_chfP[bid] = r0; g_chlP[bid] = r1; }
    } else if (bid == 8) {
        // reduce scalar partials from k_fused (256 each)
        const float r0 = block_sum(g_glP[tid],  smem8);
        const float r1 = block_sum(g_locP[tid], smem8);
        const float r2 = block_sum(g_klP[tid],  smem8);
        const float r3 = block_sum(g_c1P[tid],  smem8);
        if (tid == 0) { g_sc[0] = r0; g_sc[1] = r1; g_sc[2] = r2; g_sc[3] = r3; }
    }

    // ---- final combine in last-finishing block ----
    __shared__ bool isLast;
    __threadfence();
    if (tid == 0) isLast = (atomicAdd(&g_cnt2, 1u) == (unsigned)(EPIB - 1));
    __syncthreads();
    if (isLast) {
        float dv = (tid < EPIB) ? __ldcg(&g_dP[tid])  : 0.f;
        float sv = (tid < EPIB) ? __ldcg(&g_spP[tid]) : 0.f;
        float cf = (tid < 8) ? __ldcg(&g_chfP[tid]) : 0.f;
        float cl = (tid < 8) ? __ldcg(&g_chlP[tid]) : 0.f;
        const float dif_t = block_sum(dv, smem8);
        const float sp_t  = block_sum(sv, smem8);
        const float chf_t = block_sum(cf, smem8);
        const float chl_t = block_sum(cl, smem8);
        if (tid == 0) {
            const float gl  = __ldcg(&g_sc[0]) * (1.f / 8388608.f);
            const float loc = __ldcg(&g_sc[1]) * (1.f / 8388608.f);
            const float chf = chf_t * (1.f / 2048.f);
            const float feat = 0.3f * gl + 0.5f * loc + 0.2f * chf;

            const float kl  = __ldcg(&g_sc[2]) * 2.f;             // (/B=8) * T^2=16
            const float c1  = __ldcg(&g_sc[3]) * (2.f / 524288.f);
            const float outl = kl + c1;

            const float dif = dif_t * (1.f / 32768.f);
            const float sp  = sp_t  * (1.f / 32768.f);
            const float chl = chl_t * (1.f / 2048.f);
            const float alpha = 0.5f * (1.f + 0.5f * aw);
            const float beta  = 0.3f * (1.f - 0.3f * aw);
            const float gamma = 0.2f * (1.f + 0.5f * aw);
            const float datt = alpha * dif + beta * chl + gamma * sp;

            const float total = 0.3f * feat + 0.4f * outl + 0.3f * datt;
            if (out_size > 0) out[0] = total;
            if (out_size > 1) out[1] = feat;
            if (out_size > 2) out[2] = outl;
            if (out_size > 3) out[3] = datt;

            g_cnt2 = 0u;    // reset for next graph replay
        }
    }
}

// ---------------- launch ----------------
extern "C" void kernel_launch(void* const* d_in, const int* in_sizes, int n_in,
                              void* d_out, int out_size) {
    const float* S  = (const float*)d_in[0];   // student_features
    const float* Tt = (const float*)d_in[1];   // teacher_features
    const float* SO = (const float*)d_in[2];   // student_outputs
    const float* TO = (const float*)d_in[3];   // teacher_outputs
    const float* O1 = (const float*)d_in[4];   // opt_t1
    const float* O2 = (const float*)d_in[5];   // opt_t2
    const float* SA = (const float*)d_in[6];   // sar_t2
    const float* M  = (const float*)d_in[7];   // feature_mask
    (void)in_sizes; (void)n_in;

    k_fused<<<MAINB + KLB, TPB>>>(S, Tt, O1, O2, SA, M, SO, TO);
    k_epi<<<EPIB, 256>>>((float*)d_out, out_size);
}

// round 8
// speedup vs baseline: 1.2656x; 1.0691x over previous
#include <cuda_runtime.h>
#include <math_constants.h>

// ---------------- problem constants ----------------
#define BB 8
#define CC 256
#define HW 4096                    // 64*64
#define PIXTOT (BB*HW)             // 32768
#define TPB 256
#define MAINB 256                  // 8 batches * 32 pixel-blocks (128 px each)
#define KLB 256                    // KL blocks
#define EPIB 128                   // epilogue blocks (256 px each)

// ---------------- scratch (static; no dynamic alloc) ----------------
__device__ __align__(16) float g_chanP_s[MAINB * CC];   // [blk][c] 256KB
__device__ __align__(16) float g_chanP_t[MAINB * CC];
__device__ __align__(16) float g_od[PIXTOT];
__device__ __align__(16) float g_hd[PIXTOT];
__device__ __align__(16) float g_ssp[PIXTOT];
__device__ __align__(16) float g_tsp[PIXTOT];
__device__ __align__(16) float g_odP[MAINB];
__device__ __align__(16) float g_glP[MAINB];
__device__ __align__(16) float g_locP[MAINB];
__device__ __align__(16) float g_klP[KLB];
__device__ __align__(16) float g_c1P[KLB];
__device__ __align__(16) float g_dP[EPIB];
__device__ __align__(16) float g_spP[EPIB];
__device__ __align__(16) float g_chfP[32];
__device__ __align__(16) float g_chlP[32];
__device__ __align__(16) float g_sc[4];                 // 0 gl 1 loc 2 kl 3 c1
__device__ unsigned g_cnt2 = 0;                         // self-resetting

// ---------------- helpers ----------------
__device__ __forceinline__ float warp_sum(float v) {
#pragma unroll
    for (int o = 16; o; o >>= 1) v += __shfl_xor_sync(0xffffffffu, v, o);
    return v;
}

__device__ __forceinline__ float sigm(float x) {
    return __fdividef(1.f, 1.f + __expf(-x));
}

// cos term: x / max(|x|, 1e-8) == sign(x) when |x|>=1e-8, else x*1e8 (no MUFU)
__device__ __forceinline__ float cos_term(float a, float b) {
    const float x = a * b;
    const float s = __uint_as_float((__float_as_uint(x) & 0x80000000u) | 0x3f800000u);
    return (fabsf(x) >= 1e-8f) ? s : x * 1e8f;
}

// N-wide block reduce (256 threads, 8 warps): one sync round for all N values.
// Results valid on thread 0 in out[0..N-1]. All threads must participate.
template<int N>
__device__ __forceinline__ void block_sumN(const float* v, float (*sm)[8], float* out) {
    const int lane = threadIdx.x & 31;
    const int wid  = threadIdx.x >> 5;
    float r[N];
#pragma unroll
    for (int q = 0; q < N; q++) r[q] = warp_sum(v[q]);
    if (lane == 0) {
#pragma unroll
        for (int q = 0; q < N; q++) sm[q][wid] = r[q];
    }
    __syncthreads();
    if (threadIdx.x == 0) {
#pragma unroll
        for (int q = 0; q < N; q++) {
            float s = 0.f;
#pragma unroll
            for (int i = 0; i < 8; i++) s += sm[q][i];
            out[q] = s;
        }
    }
    __syncthreads();
}

// ---------------- K1: fused streamer (all channels in-block) + KL ----------------
__global__ __launch_bounds__(TPB) void k_fused(
    const float* __restrict__ S, const float* __restrict__ Tt,
    const float* __restrict__ O1, const float* __restrict__ O2,
    const float* __restrict__ SA, const float* __restrict__ M,
    const float* __restrict__ SO, const float* __restrict__ TO)
{
    __shared__ float smN[4][8];
    float red[4];

    if (blockIdx.x < MAINB) {
        // ---- main role: 128 contiguous pixels, all 256 channels ----
        __shared__ float sAcc[8][9][128];     // [warp][quant][pixel] 36 KB
        const int blk = blockIdx.x;
        const int b   = blk >> 5;             // 0..7
        const int pb  = blk & 31;             // 0..31
        const int px0 = pb * 128;
        const int w    = threadIdx.x >> 5;    // 0..7
        const int lane = threadIdx.x & 31;
        const size_t pbase = (size_t)b * CC * HW + px0 + lane * 4;

        float sqo[4]={0,0,0,0}, cso[4]={0,0,0,0}, sqh[4]={0,0,0,0}, csh[4]={0,0,0,0};
        float ssm[4]={0,0,0,0}, tsm[4]={0,0,0,0}, gl[4]={0,0,0,0};
        float smx[4]={-CUDART_INF_F,-CUDART_INF_F,-CUDART_INF_F,-CUDART_INF_F};
        float tmx[4]={-CUDART_INF_F,-CUDART_INF_F,-CUDART_INF_F,-CUDART_INF_F};

#pragma unroll 4
        for (int j = 0; j < CC / 8; j++) {    // warp w handles channel c = w + 8j
            const int c = w + (j << 3);
            const size_t base = pbase + (size_t)c * HW;
            const float4 s  = __ldcg((const float4*)(S  + base));
            const float4 t  = __ldcg((const float4*)(Tt + base));
            const float4 a  = __ldcg((const float4*)(O1 + base));
            const float4 b2 = __ldcg((const float4*)(O2 + base));
            const float4 c2 = __ldcg((const float4*)(SA + base));
            const float sv[4] = {s.x, s.y, s.z, s.w};
            const float tv[4] = {t.x, t.y, t.z, t.w};
            const float av[4] = {a.x, a.y, a.z, a.w};
            const float bv[4] = {b2.x, b2.y, b2.z, b2.w};
            const float cv[4] = {c2.x, c2.y, c2.z, c2.w};
#pragma unroll
            for (int k = 0; k < 4; k++) {
                const float d = sv[k] - tv[k];
                gl[k]  += d * d;
                ssm[k] += sv[k];
                tsm[k] += tv[k];
                smx[k] = fmaxf(smx[k], sv[k]);
                tmx[k] = fmaxf(tmx[k], tv[k]);
                const float d1 = av[k] - bv[k];
                sqo[k] += d1 * d1;
                cso[k] += cos_term(av[k], bv[k]);
                const float d2 = av[k] - cv[k];
                sqh[k] += d2 * d2;
                csh[k] += cos_term(av[k], cv[k]);
            }
            // channel sum over this block's 128 pixels (complete for channel c)
            const float sred = warp_sum(sv[0] + sv[1] + sv[2] + sv[3]);
            const float tred = warp_sum(tv[0] + tv[1] + tv[2] + tv[3]);
            if (lane == 0) {
                g_chanP_s[blk * CC + c] = sred;
                g_chanP_t[blk * CC + c] = tred;
            }
        }

        // in-block cross-warp combine via smem transpose
        ((float4*)sAcc[w][0])[lane] = make_float4(sqo[0], sqo[1], sqo[2], sqo[3]);
        ((float4*)sAcc[w][1])[lane] = make_float4(cso[0], cso[1], cso[2], cso[3]);
        ((float4*)sAcc[w][2])[lane] = make_float4(sqh[0], sqh[1], sqh[2], sqh[3]);
        ((float4*)sAcc[w][3])[lane] = make_float4(csh[0], csh[1], csh[2], csh[3]);
        ((float4*)sAcc[w][4])[lane] = make_float4(ssm[0], ssm[1], ssm[2], ssm[3]);
        ((float4*)sAcc[w][5])[lane] = make_float4(tsm[0], tsm[1], tsm[2], tsm[3]);
        ((float4*)sAcc[w][6])[lane] = make_float4(gl[0],  gl[1],  gl[2],  gl[3]);
        ((float4*)sAcc[w][7])[lane] = make_float4(smx[0], smx[1], smx[2], smx[3]);
        ((float4*)sAcc[w][8])[lane] = make_float4(tmx[0], tmx[1], tmx[2], tmx[3]);
        __syncthreads();

        float vals[3] = {0.f, 0.f, 0.f};    // od, gl, loc partials
        if (threadIdx.x < 128) {
            const int p = threadIdx.x;
            float aSqo=0.f, aCso=0.f, aSqh=0.f, aCsh=0.f, aSsm=0.f, aTsm=0.f, aGl=0.f;
            float aSmx=-CUDART_INF_F, aTmx=-CUDART_INF_F;
#pragma unroll
            for (int w2 = 0; w2 < 8; w2++) {
                aSqo += sAcc[w2][0][p];
                aCso += sAcc[w2][1][p];
                aSqh += sAcc[w2][2][p];
                aCsh += sAcc[w2][3][p];
                aSsm += sAcc[w2][4][p];
                aTsm += sAcc[w2][5][p];
                aGl  += sAcc[w2][6][p];
                aSmx = fmaxf(aSmx, sAcc[w2][7][p]);
                aTmx = fmaxf(aTmx, sAcc[w2][8][p]);
            }
            const float l2o = sqrtf(aSqo + 1e-6f);
            const float od  = (l2o + 1.f - aCso * (1.f / 256.f)) * sigm(l2o * 5.f);
            const float l2h = sqrtf(aSqh + 1e-6f);
            const float hd  = (l2h + 1.f - aCsh * (1.f / 256.f)) * sigm(l2h * 5.f);
            const int gpix = b * HW + px0 + p;
            g_od[gpix]  = od;
            g_hd[gpix]  = hd;
            g_ssp[gpix] = sigm(aSsm * (1.f / 256.f) + aSmx);
            g_tsp[gpix] = sigm(aTsm * (1.f / 256.f) + aTmx);
            const float m = __ldcg(M + gpix);
            vals[0] = od;
            vals[1] = aGl;
            vals[2] = m * m * aGl;
        }
        block_sumN<3>(vals, smN, red);
        if (threadIdx.x == 0) {
            g_odP[blk]  = red[0];
            g_glP[blk]  = red[1];
            g_locP[blk] = red[2];
        }
    } else {
        // ---- KL role ----
        const int kid = blockIdx.x - MAINB;   // 0..255
        float kls = 0.f, c1s = 0.f;
#pragma unroll
        for (int it = 0; it < 2; it++) {
            const int idx = kid * 512 + it * 256 + threadIdx.x;   // 0..131071
            const int b  = idx >> 14;
            const int i4 = idx & 16383;
            const size_t base = (size_t)b * 32768 + i4;

            const float4 s0 = __ldcg((const float4*)SO + base);
            const float4 s1 = __ldcg((const float4*)SO + base + 16384);
            const float4 t0 = __ldcg((const float4*)TO + base);
            const float4 t1 = __ldcg((const float4*)TO + base + 16384);
            const float s0v[4] = {s0.x, s0.y, s0.z, s0.w};
            const float s1v[4] = {s1.x, s1.y, s1.z, s1.w};
            const float t0v[4] = {t0.x, t0.y, t0.z, t0.w};
            const float t1v[4] = {t1.x, t1.y, t1.z, t1.w};
#pragma unroll
            for (int k = 0; k < 4; k++) {
                const float a0 = s0v[k] * 0.25f, a1 = s1v[k] * 0.25f;
                const float mx = fmaxf(a0, a1);
                const float lse = mx + __logf(__expf(a0 - mx) + __expf(a1 - mx));
                const float ls0 = a0 - lse, ls1 = a1 - lse;
                const float b0 = t0v[k] * 0.25f, b1 = t1v[k] * 0.25f;
                const float mt = fmaxf(b0, b1);
                const float e0 = __expf(b0 - mt), e1 = __expf(b1 - mt);
                const float Z = e0 + e1;
                const float lZ = __logf(Z);
                const float rz = __fdividef(1.f, Z);
                const float p0 = e0 * rz, p1 = e1 * rz;
                kls += p0 * ((b0 - mt - lZ) - ls0) + p1 * ((b1 - mt - lZ) - ls1);
                const float dd = __expf(ls1) - p1;
                c1s += dd * dd;
            }
        }
        const float vals[2] = {kls, c1s};
        block_sumN<2>(vals, smN, red);
        if (threadIdx.x == 0) { g_klP[kid] = red[0]; g_c1P[kid] = red[1]; }
    }
}

// ---------------- K2: epilogue (prefetch-first, latency-optimized) ----------------
__global__ __launch_bounds__(256) void k_epi(float* out, int out_size) {
    __shared__ float smN[4][8];
    __shared__ float sred[4];
    float red[4];
    const int tid = threadIdx.x;
    const int bid = blockIdx.x;

    // ======== phase 0: issue ALL independent global loads up front ========
    const int pix = bid * 256 + tid;            // 0..32767
    const float od  = __ldcg(g_od  + pix);
    const float hd  = __ldcg(g_hd  + pix);
    const float ssp = __ldcg(g_ssp + pix);
    const float tsp = __ldcg(g_tsp + pix);
    const float odp = g_odP[tid];               // 256 partials, L2-resident

    // channel-loss loads: blocks 0..31, quad (4 threads) per (b,c) pair
    float ssl[8], ttl[8];
    const int q  = pix >> 2;                    // global quad id (0..2047 for bid<32)
    const int cb = q >> 8;                      // batch
    const int cc = q & 255;                     // channel
    const int p0 = (tid & 3) * 8;               // this thread's 8 partials
    if (bid < 32) {
#pragma unroll
        for (int i = 0; i < 8; i++) {
            const int idx = ((cb << 5) + p0 + i) * CC + cc;
            ssl[i] = __ldcg(g_chanP_s + idx);
            ttl[i] = __ldcg(g_chanP_t + idx);
        }
    }
    // scalar-partial loads: block 32
    float sgl = 0.f, sloc = 0.f, skl = 0.f, sc1 = 0.f;
    if (bid == 32) {
        sgl  = __ldcg(g_glP  + tid);
        sloc = __ldcg(g_locP + tid);
        skl  = __ldcg(g_klP  + tid);
        sc1  = __ldcg(g_c1P  + tid);
    }

    // ======== phase 1: mean(opt_diff) (overlaps with loads above) ========
    {
        const float v[1] = {odp};
        block_sumN<1>(v, smN, red);
        if (tid == 0) sred[0] = red[0];
        __syncthreads();
    }
    const float mean_od = sred[0] * (1.f / 32768.f);
    const float thr = mean_od * 1.5f;
    const float aw  = sigm(mean_od * 10.f);

    // ======== phase 2: masked losses ========
    const float mask = (od > thr) ? 1.f : 0.f;
    const float w = mask * 2.f + (1.f - mask) * 0.5f;
    const float dd = (hd - od) * w;
    const float amp = 1.f + aw * mask;
    const float sd = (ssp - tsp) * amp;

    // channel-loss math (quad-combine via shuffles)
    float chf = 0.f, chl = 0.f;
    if (bid < 32) {
        float ss = 0.f, tt = 0.f;
#pragma unroll
        for (int i = 0; i < 8; i++) { ss += ssl[i]; tt += ttl[i]; }
        ss += __shfl_xor_sync(0xffffffffu, ss, 1);
        ss += __shfl_xor_sync(0xffffffffu, ss, 2);
        tt += __shfl_xor_sync(0xffffffffu, tt, 1);
        tt += __shfl_xor_sync(0xffffffffu, tt, 2);
        if ((tid & 3) == 0) {
            const float ms = ss * (1.f / (float)HW);
            const float mt = tt * (1.f / (float)HW);
            const float d  = ms - mt;
            const float e  = sigm(ms) - sigm(mt);
            chf = d * d;
            chl = e * e;
        }
    }

    {
        const float v[4] = {dd * dd, sd * sd, chf, chl};
        block_sumN<4>(v, smN, red);
        if (tid == 0) {
            g_dP[bid]  = red[0];
            g_spP[bid] = red[1];
            if (bid < 32) { g_chfP[bid] = red[2]; g_chlP[bid] = red[3]; }
        }
    }
    if (bid == 32) {
        const float v[4] = {sgl, sloc, skl, sc1};
        block_sumN<4>(v, smN, red);
        if (tid == 0) {
            g_sc[0] = red[0]; g_sc[1] = red[1]; g_sc[2] = red[2]; g_sc[3] = red[3];
        }
    }

    // ======== phase 3: final combine in last-finishing block ========
    __shared__ bool isLast;
    __threadfence();
    if (tid == 0) isLast = (atomicAdd(&g_cnt2, 1u) == (unsigned)(EPIB - 1));
    __syncthreads();
    if (isLast) {
        const float dv = (tid < EPIB) ? __ldcg(&g_dP[tid])  : 0.f;
        const float sv = (tid < EPIB) ? __ldcg(&g_spP[tid]) : 0.f;
        const float cf = (tid < 32) ? __ldcg(&g_chfP[tid]) : 0.f;
        const float cl = (tid < 32) ? __ldcg(&g_chlP[tid]) : 0.f;
        const float v[4] = {dv, sv, cf, cl};
        block_sumN<4>(v, smN, red);
        if (tid == 0) {
            const float gl  = __ldcg(&g_sc[0]) * (1.f / 8388608.f);
            const float loc = __ldcg(&g_sc[1]) * (1.f / 8388608.f);
            const float chft = red[2] * (1.f / 2048.f);
            const float feat = 0.3f * gl + 0.5f * loc + 0.2f * chft;

            const float kl  = __ldcg(&g_sc[2]) * 2.f;             // (/B=8) * T^2=16
            const float c1  = __ldcg(&g_sc[3]) * (2.f / 524288.f);
            const float outl = kl + c1;

            const float dif = red[0] * (1.f / 32768.f);
            const float sp  = red[1] * (1.f / 32768.f);
            const float chlt = red[3] * (1.f / 2048.f);
            const float alpha = 0.5f * (1.f + 0.5f * aw);
            const float beta  = 0.3f * (1.f - 0.3f * aw);
            const float gamma = 0.2f * (1.f + 0.5f * aw);
            const float datt = alpha * dif + beta * chlt + gamma * sp;

            const float total = 0.3f * feat + 0.4f * outl + 0.3f * datt;
            if (out_size > 0) out[0] = total;
            if (out_size > 1) out[1] = feat;
            if (out_size > 2) out[2] = outl;
            if (out_size > 3) out[3] = datt;

            g_cnt2 = 0u;    // reset for next graph replay
        }
    }
}

// ---------------- launch ----------------
extern "C" void kernel_launch(void* const* d_in, const int* in_sizes, int n_in,
                              void* d_out, int out_size) {
    const float* S  = (const float*)d_in[0];   // student_features
    const float* Tt = (const float*)d_in[1];   // teacher_features
    const float* SO = (const float*)d_in[2];   // student_outputs
    const float* TO = (const float*)d_in[3];   // teacher_outputs
    const float* O1 = (const float*)d_in[4];   // opt_t1
    const float* O2 = (const float*)d_in[5];   // opt_t2
    const float* SA = (const float*)d_in[6];   // sar_t2
    const float* M  = (const float*)d_in[7];   // feature_mask
    (void)in_sizes; (void)n_in;

    k_fused<<<MAINB + KLB, TPB>>>(S, Tt, O1, O2, SA, M, SO, TO);
    k_epi<<<EPIB, 256>>>((float*)d_out, out_size);
}

// round 10
// speedup vs baseline: 1.7099x; 1.3511x over previous
#include <cuda_runtime.h>
#include <math_constants.h>

// ---------------- problem constants ----------------
#define BB 8
#define CC 256
#define HW 4096                    // 64*64
#define PIXTOT (BB*HW)             // 32768
#define TPB 256
#define FUSEB 256                  // uniform blocks: each = 1 main tile + 1 KL chunk
#define EPIB 128                   // epilogue blocks (256 px each)

// ---------------- scratch (static; no dynamic alloc) ----------------
__device__ __align__(16) float g_od[PIXTOT];            // opt diff map
__device__ __align__(16) float g_A[PIXTOT];             // (hd-od)^2
__device__ __align__(16) float g_B[PIXTOT];             // (ssp-tsp)^2
__device__ __align__(16) float g_chan_s[BB*CC];         // atomic accum, epi-reset
__device__ __align__(16) float g_chan_t[BB*CC];
__device__ __align__(16) float g_odP[FUSEB];
__device__ __align__(16) float g_glP[FUSEB];
__device__ __align__(16) float g_locP[FUSEB];
__device__ __align__(16) float g_klP[FUSEB];
__device__ __align__(16) float g_c1P[FUSEB];
__device__ __align__(16) float g_p4[4][EPIB];           // A, Asel, B, Bsel partials
__device__ __align__(16) float g_chfP[8];
__device__ __align__(16) float g_chlP[8];
__device__ __align__(16) float g_sc[4];                 // 0 gl 1 loc 2 kl 3 c1
__device__ unsigned g_cnt2 = 0;                         // self-resetting

// ---------------- helpers ----------------
__device__ __forceinline__ float warp_sum(float v) {
#pragma unroll
    for (int o = 16; o; o >>= 1) v += __shfl_xor_sync(0xffffffffu, v, o);
    return v;
}

__device__ __forceinline__ float sigm(float x) {
    return __fdividef(1.f, 1.f + __expf(-x));
}

// cos term: x / max(|x|, 1e-8) == sign(x) when |x|>=1e-8, else x*1e8 (no MUFU)
__device__ __forceinline__ float cos_term(float a, float b) {
    const float x = a * b;
    const float s = __uint_as_float((__float_as_uint(x) & 0x80000000u) | 0x3f800000u);
    return (fabsf(x) >= 1e-8f) ? s : x * 1e8f;
}

// N-wide block reduce (256 threads, 8 warps): one sync round for all N values.
template<int N>
__device__ __forceinline__ void block_sumN(const float* v, float (*sm)[8], float* out) {
    const int lane = threadIdx.x & 31;
    const int wid  = threadIdx.x >> 5;
    float r[N];
#pragma unroll
    for (int q = 0; q < N; q++) r[q] = warp_sum(v[q]);
    if (lane == 0) {
#pragma unroll
        for (int q = 0; q < N; q++) sm[q][wid] = r[q];
    }
    __syncthreads();
    if (threadIdx.x == 0) {
#pragma unroll
        for (int q = 0; q < N; q++) {
            float s = 0.f;
#pragma unroll
            for (int i = 0; i < 8; i++) s += sm[q][i];
            out[q] = s;
        }
    }
    __syncthreads();
}

// ---------------- K1: uniform fused streamer: main tile + KL chunk per block ----------------
__global__ __launch_bounds__(TPB, 2) void k_fused(
    const float* __restrict__ S, const float* __restrict__ Tt,
    const float* __restrict__ O1, const float* __restrict__ O2,
    const float* __restrict__ SA, const float* __restrict__ M,
    const float* __restrict__ SO, const float* __restrict__ TO)
{
    __shared__ float smN[6][8];
    __shared__ float sAcc[8][9][128];     // [warp][quant][pixel] 36 KB
    float red[6];
    const int blk = blockIdx.x;

    // ======== role A: main tile (128 contiguous pixels, all 256 channels) ========
    {
        const int b   = blk >> 5;             // 0..7
        const int pb  = blk & 31;             // 0..31
        const int px0 = pb * 128;
        const int w    = threadIdx.x >> 5;    // 0..7
        const int lane = threadIdx.x & 31;
        const size_t pbase = (size_t)b * CC * HW + px0 + lane * 4;

        float sqo[4]={0,0,0,0}, cso[4]={0,0,0,0}, sqh[4]={0,0,0,0}, csh[4]={0,0,0,0};
        float ssm[4]={0,0,0,0}, tsm[4]={0,0,0,0}, gl[4]={0,0,0,0};
        float smx[4]={-CUDART_INF_F,-CUDART_INF_F,-CUDART_INF_F,-CUDART_INF_F};
        float tmx[4]={-CUDART_INF_F,-CUDART_INF_F,-CUDART_INF_F,-CUDART_INF_F};

#pragma unroll 4
        for (int j = 0; j < CC / 8; j++) {    // warp w handles channel c = w + 8j
            const int c = w + (j << 3);
            const size_t base = pbase + (size_t)c * HW;
            const float4 s  = __ldcg((const float4*)(S  + base));
            const float4 t  = __ldcg((const float4*)(Tt + base));
            const float4 a  = __ldcg((const float4*)(O1 + base));
            const float4 b2 = __ldcg((const float4*)(O2 + base));
            const float4 c2 = __ldcg((const float4*)(SA + base));
            const float sv[4] = {s.x, s.y, s.z, s.w};
            const float tv[4] = {t.x, t.y, t.z, t.w};
            const float av[4] = {a.x, a.y, a.z, a.w};
            const float bv[4] = {b2.x, b2.y, b2.z, b2.w};
            const float cv[4] = {c2.x, c2.y, c2.z, c2.w};
#pragma unroll
            for (int k = 0; k < 4; k++) {
                const float d = sv[k] - tv[k];
                gl[k]  += d * d;
                ssm[k] += sv[k];
                tsm[k] += tv[k];
                smx[k] = fmaxf(smx[k], sv[k]);
                tmx[k] = fmaxf(tmx[k], tv[k]);
                const float d1 = av[k] - bv[k];
                sqo[k] += d1 * d1;
                cso[k] += cos_term(av[k], bv[k]);
                const float d2 = av[k] - cv[k];
                sqh[k] += d2 * d2;
                csh[k] += cos_term(av[k], cv[k]);
            }
            // channel sum over this block's 128 pixels -> atomic accumulate
            const float sred = warp_sum(sv[0] + sv[1] + sv[2] + sv[3]);
            const float tred = warp_sum(tv[0] + tv[1] + tv[2] + tv[3]);
            if (lane == 0) {
                atomicAdd(&g_chan_s[b * CC + c], sred);
                atomicAdd(&g_chan_t[b * CC + c], tred);
            }
        }

        // in-block cross-warp combine via smem transpose
        ((float4*)sAcc[w][0])[lane] = make_float4(sqo[0], sqo[1], sqo[2], sqo[3]);
        ((float4*)sAcc[w][1])[lane] = make_float4(cso[0], cso[1], cso[2], cso[3]);
        ((float4*)sAcc[w][2])[lane] = make_float4(sqh[0], sqh[1], sqh[2], sqh[3]);
        ((float4*)sAcc[w][3])[lane] = make_float4(csh[0], csh[1], csh[2], csh[3]);
        ((float4*)sAcc[w][4])[lane] = make_float4(ssm[0], ssm[1], ssm[2], ssm[3]);
        ((float4*)sAcc[w][5])[lane] = make_float4(tsm[0], tsm[1], tsm[2], tsm[3]);
        ((float4*)sAcc[w][6])[lane] = make_float4(gl[0],  gl[1],  gl[2],  gl[3]);
        ((float4*)sAcc[w][7])[lane] = make_float4(smx[0], smx[1], smx[2], smx[3]);
        ((float4*)sAcc[w][8])[lane] = make_float4(tmx[0], tmx[1], tmx[2], tmx[3]);
        __syncthreads();

        float vals[3] = {0.f, 0.f, 0.f};    // od, gl, loc partials
        if (threadIdx.x < 128) {
            const int p = threadIdx.x;
            float aSqo=0.f, aCso=0.f, aSqh=0.f, aCsh=0.f, aSsm=0.f, aTsm=0.f, aGl=0.f;
            float aSmx=-CUDART_INF_F, aTmx=-CUDART_INF_F;
#pragma unroll
            for (int w2 = 0; w2 < 8; w2++) {
                aSqo += sAcc[w2][0][p];
                aCso += sAcc[w2][1][p];
                aSqh += sAcc[w2][2][p];
                aCsh += sAcc[w2][3][p];
                aSsm += sAcc[w2][4][p];
                aTsm += sAcc[w2][5][p];
                aGl  += sAcc[w2][6][p];
                aSmx = fmaxf(aSmx, sAcc[w2][7][p]);
                aTmx = fmaxf(aTmx, sAcc[w2][8][p]);
            }
            const float l2o = sqrtf(aSqo + 1e-6f);
            const float od  = (l2o + 1.f - aCso * (1.f / 256.f)) * sigm(l2o * 5.f);
            const float l2h = sqrtf(aSqh + 1e-6f);
            const float hd  = (l2h + 1.f - aCsh * (1.f / 256.f)) * sigm(l2h * 5.f);
            const float ssp = sigm(aSsm * (1.f / 256.f) + aSmx);
            const float tsp = sigm(aTsm * (1.f / 256.f) + aTmx);
            const int gpix = b * HW + px0 + p;
            const float dA = hd - od;
            const float dB = ssp - tsp;
            g_od[gpix] = od;
            g_A[gpix]  = dA * dA;
            g_B[gpix]  = dB * dB;
            const float m = __ldcg(M + gpix);
            vals[0] = od;
            vals[1] = aGl;
            vals[2] = m * m * aGl;
        }
        block_sumN<3>(vals, smN, red);
        if (threadIdx.x == 0) {
            g_odP[blk]  = red[0];
            g_glP[blk]  = red[1];
            g_locP[blk] = red[2];
        }
    }

    // ======== role B: KL chunk (uniform per block) ========
    {
        float kls = 0.f, c1s = 0.f;
#pragma unroll
        for (int it = 0; it < 2; it++) {
            const int idx = blk * 512 + it * 256 + threadIdx.x;   // 0..131071
            const int b  = idx >> 14;
            const int i4 = idx & 16383;
            const size_t base = (size_t)b * 32768 + i4;

            const float4 s0 = __ldcg((const float4*)SO + base);
            const float4 s1 = __ldcg((const float4*)SO + base + 16384);
            const float4 t0 = __ldcg((const float4*)TO + base);
            const float4 t1 = __ldcg((const float4*)TO + base + 16384);
            const float s0v[4] = {s0.x, s0.y, s0.z, s0.w};
            const float s1v[4] = {s1.x, s1.y, s1.z, s1.w};
            const float t0v[4] = {t0.x, t0.y, t0.z, t0.w};
            const float t1v[4] = {t1.x, t1.y, t1.z, t1.w};
#pragma unroll
            for (int k = 0; k < 4; k++) {
                const float a0 = s0v[k] * 0.25f, a1 = s1v[k] * 0.25f;
                const float mx = fmaxf(a0, a1);
                const float lse = mx + __logf(__expf(a0 - mx) + __expf(a1 - mx));
                const float ls0 = a0 - lse, ls1 = a1 - lse;
                const float b0 = t0v[k] * 0.25f, b1 = t1v[k] * 0.25f;
                const float mt = fmaxf(b0, b1);
                const float e0 = __expf(b0 - mt), e1 = __expf(b1 - mt);
                const float Z = e0 + e1;
                const float lZ = __logf(Z);
                const float rz = __fdividef(1.f, Z);
                const float p0 = e0 * rz, p1 = e1 * rz;
                kls += p0 * ((b0 - mt - lZ) - ls0) + p1 * ((b1 - mt - lZ) - ls1);
                const float dd = __expf(ls1) - p1;
                c1s += dd * dd;
            }
        }
        const float vals[2] = {kls, c1s};
        block_sumN<2>(vals, smN, red);
        if (threadIdx.x == 0) { g_klP[blk] = red[0]; g_c1P[blk] = red[1]; }
    }
}

// ---------------- K2: epilogue (selection pass + final combine) ----------------
__global__ __launch_bounds__(256) void k_epi(float* out, int out_size) {
    __shared__ float smN[6][8];
    __shared__ float sred[1];
    float red[6];
    const int tid = threadIdx.x;
    const int bid = blockIdx.x;

    // ---- phase 0: issue all independent loads ----
    const int pix = bid * 256 + tid;            // 0..32767
    const float od = __ldcg(g_od + pix);
    const float A  = __ldcg(g_A  + pix);
    const float B  = __ldcg(g_B  + pix);
    const float odp = g_odP[tid];               // 256 partials

    float cs = 0.f, ct = 0.f;                   // chan loads (blocks 0..7)
    if (bid < 8) {
        cs = __ldcg(g_chan_s + bid * 256 + tid);
        ct = __ldcg(g_chan_t + bid * 256 + tid);
    }
    float sgl = 0.f, sloc = 0.f, skl = 0.f, sc1 = 0.f;
    if (bid == 8) {
        sgl  = __ldcg(g_glP  + tid);
        sloc = __ldcg(g_locP + tid);
        skl  = __ldcg(g_klP  + tid);
        sc1  = __ldcg(g_c1P  + tid);
    }

    // ---- phase 1: mean(opt_diff) ----
    {
        const float v[1] = {odp};
        block_sumN<1>(v, smN, red);
        if (tid == 0) sred[0] = red[0];
        __syncthreads();
    }
    const float mean_od = sred[0] * (1.f / 32768.f);
    const float thr = mean_od * 1.5f;
    const float aw  = sigm(mean_od * 10.f);

    // ---- phase 2: conditional sums + role work ----
    const float sel = (od > thr) ? 1.f : 0.f;
    {
        const float v[4] = {A, sel * A, B, sel * B};
        block_sumN<4>(v, smN, red);
        if (tid == 0) {
            g_p4[0][bid] = red[0];
            g_p4[1][bid] = red[1];
            g_p4[2][bid] = red[2];
            g_p4[3][bid] = red[3];
        }
    }
    if (bid < 8) {
        const float ms = cs * (1.f / (float)HW);
        const float mt = ct * (1.f / (float)HW);
        const float d  = ms - mt;
        const float e  = sigm(ms) - sigm(mt);
        const float v[2] = {d * d, e * e};
        block_sumN<2>(v, smN, red);
        if (tid == 0) { g_chfP[bid] = red[0]; g_chlP[bid] = red[1]; }
        // reset chan accumulators for next graph replay
        g_chan_s[bid * 256 + tid] = 0.f;
        g_chan_t[bid * 256 + tid] = 0.f;
    } else if (bid == 8) {
        const float v[4] = {sgl, sloc, skl, sc1};
        block_sumN<4>(v, smN, red);
        if (tid == 0) {
            g_sc[0] = red[0]; g_sc[1] = red[1]; g_sc[2] = red[2]; g_sc[3] = red[3];
        }
    }

    // ---- phase 3: final combine in last-finishing block ----
    __shared__ bool isLast;
    __threadfence();
    if (tid == 0) isLast = (atomicAdd(&g_cnt2, 1u) == (unsigned)(EPIB - 1));
    __syncthreads();
    if (isLast) {
        const float vA  = (tid < EPIB) ? __ldcg(&g_p4[0][tid]) : 0.f;
        const float vAs = (tid < EPIB) ? __ldcg(&g_p4[1][tid]) : 0.f;
        const float vB  = (tid < EPIB) ? __ldcg(&g_p4[2][tid]) : 0.f;
        const float vBs = (tid < EPIB) ? __ldcg(&g_p4[3][tid]) : 0.f;
        const float cf  = (tid < 8) ? __ldcg(&g_chfP[tid]) : 0.f;
        const float cl  = (tid < 8) ? __ldcg(&g_chlP[tid]) : 0.f;
        const float v[6] = {vA, vAs, vB, vBs, cf, cl};
        block_sumN<6>(v, smN, red);
        if (tid == 0) {
            const float gl  = __ldcg(&g_sc[0]) * (1.f / 8388608.f);
            const float loc = __ldcg(&g_sc[1]) * (1.f / 8388608.f);
            const float chf = red[4] * (1.f / 2048.f);
            const float feat = 0.3f * gl + 0.5f * loc + 0.2f * chf;

            const float kl  = __ldcg(&g_sc[2]) * 2.f;             // (/B=8) * T^2=16
            const float c1  = __ldcg(&g_sc[3]) * (2.f / 524288.f);
            const float outl = kl + c1;

            // dsum = sum w^2*A, w^2 in {4, 0.25}  -> 0.25*sumA + 3.75*sumA_sel
            const float dif = (0.25f * red[0] + 3.75f * red[1]) * (1.f / 32768.f);
            // spsum = sum amp^2*B, amp^2 in {(1+aw)^2, 1}
            const float ampd = (1.f + aw) * (1.f + aw) - 1.f;
            const float sp  = (red[2] + ampd * red[3]) * (1.f / 32768.f);
            const float chl = red[5] * (1.f / 2048.f);
            const float alpha = 0.5f * (1.f + 0.5f * aw);
            const float beta  = 0.3f * (1.f - 0.3f * aw);
            const float gamma = 0.2f * (1.f + 0.5f * aw);
            const float datt = alpha * dif + beta * chl + gamma * sp;

            const float total = 0.3f * feat + 0.4f * outl + 0.3f * datt;
            if (out_size > 0) out[0] = total;
            if (out_size > 1) out[1] = feat;
            if (out_size > 2) out[2] = outl;
            if (out_size > 3) out[3] = datt;

            g_cnt2 = 0u;    // reset for next graph replay
        }
    }
}

// ---------------- launch ----------------
extern "C" void kernel_launch(void* const* d_in, const int* in_sizes, int n_in,
                              void* d_out, int out_size) {
    const float* S  = (const float*)d_in[0];   // student_features
    const float* Tt = (const float*)d_in[1];   // teacher_features
    const float* SO = (const float*)d_in[2];   // student_outputs
    const float* TO = (const float*)d_in[3];   // teacher_outputs
    const float* O1 = (const float*)d_in[4];   // opt_t1
    const float* O2 = (const float*)d_in[5];   // opt_t2
    const float* SA = (const float*)d_in[6];   // sar_t2
    const float* M  = (const float*)d_in[7];   // feature_mask
    (void)in_sizes; (void)n_in;

    k_fused<<<FUSEB, TPB>>>(S, Tt, O1, O2, SA, M, SO, TO);
    k_epi<<<EPIB, 256>>>((float*)d_out, out_size);
}